// round 14
// baseline (speedup 1.0000x reference)
#include <cuda_runtime.h>
#include <math.h>
#include <stdint.h>

// Problem constants
#define Bsz 2
#define Tn  1024
#define En  512
#define Hn  8
#define Dn  64
#define TC  64                 // chunk length
#define NCH (Tn / TC)          // 16 chunks
#define NBH (Bsz * Hn)         // 16 (b,h) pairs
#define STATE_STRIDE 8320      // Scos(4096) + Ssin(4096) + zc(64) + zs(64)
#define PI_2f 1.5707963267948966f
#define EPSf  1e-6f

// ---------------- scratch (no runtime allocation allowed) ----------------
__device__ float g_qkv[Bsz * Tn * 3 * En];                 // [2048][1536]  12MB
__device__ float g_state[NBH * NCH * STATE_STRIDE];        // 8.1MB
__device__ float g_attn[Bsz * Tn * En];                    // [2048][512]   4MB

// =========================================================================
// tf32 mma helpers
// =========================================================================
__device__ __forceinline__ uint32_t f2tf32(float x) {
    uint32_t r;
    asm("cvt.rna.tf32.f32 %0, %1;" : "=r"(r) : "f"(x));
    return r;
}

__device__ __forceinline__ void split_tf32(float x, uint32_t& hi, uint32_t& lo) {
    hi = f2tf32(x);
    float rem = x - __uint_as_float(hi);
    lo = f2tf32(rem);
}

__device__ __forceinline__ void mma_tf32(float c[4], const uint32_t a[4],
                                         const uint32_t b[2]) {
    asm volatile(
        "mma.sync.aligned.m16n8k8.row.col.f32.tf32.tf32.f32 "
        "{%0,%1,%2,%3}, {%4,%5,%6,%7}, {%8,%9}, {%0,%1,%2,%3};\n"
        : "+f"(c[0]), "+f"(c[1]), "+f"(c[2]), "+f"(c[3])
        : "r"(a[0]), "r"(a[1]), "r"(a[2]), "r"(a[3]),
          "r"(b[0]), "r"(b[1]));
}

// =========================================================================
// K1/K5: C[M,N] = A[M,K] @ B[N,K]^T + bias[N]   (tf32 tensor cores, 3-pass
// precision split). BM=128, BK=16, 256 threads (8 warps as 2x4),
// warp tile 64 x (BN/4). Register-prefetch double buffering.
// =========================================================================
template<int BN>
__global__ __launch_bounds__(256) void gemm_tf32_nt_bias(
    const float* __restrict__ A, const float* __restrict__ Bm,
    const float* __restrict__ bias, float* __restrict__ C,
    int M, int N, int K)
{
    constexpr int BM = 128, BK = 16;
    constexpr int NT = BN / 32;                 // n8-tiles per warp
    constexpr int A_IT = (BM * BK) / (4 * 256); // 2
    constexpr int B_IT = (BN * BK) / (4 * 256); // 2 or 1

    __shared__ uint32_t As_hi[BM][BK + 4], As_lo[BM][BK + 4];
    __shared__ uint32_t Bs_hi[BN][BK + 4], Bs_lo[BN][BK + 4];

    const int tid = threadIdx.x;
    const int m0 = blockIdx.y * BM;
    const int n0 = blockIdx.x * BN;
    const int warp = tid >> 5, lane = tid & 31;
    const int g = lane >> 2, q = lane & 3;
    const int wm0 = (warp >> 2) * 64;
    const int wn0 = (warp & 3) * (BN / 4);

    float4 areg[A_IT], breg[B_IT];

    float acc[4][NT][4];
#pragma unroll
    for (int i = 0; i < 4; i++)
#pragma unroll
        for (int j = 0; j < NT; j++)
#pragma unroll
            for (int u = 0; u < 4; u++) acc[i][j][u] = 0.f;

    // prime the pipeline
#pragma unroll
    for (int it = 0; it < A_IT; it++) {
        int idx = it * 256 + tid;
        int row = idx >> 2, c4 = (idx & 3) * 4;
        areg[it] = *reinterpret_cast<const float4*>(&A[(size_t)(m0 + row) * K + c4]);
    }
#pragma unroll
    for (int it = 0; it < B_IT; it++) {
        int idx = it * 256 + tid;
        int row = idx >> 2, c4 = (idx & 3) * 4;
        breg[it] = *reinterpret_cast<const float4*>(&Bm[(size_t)(n0 + row) * K + c4]);
    }

    for (int k0 = 0; k0 < K; k0 += BK) {
        // stage regs -> smem with tf32 split
#pragma unroll
        for (int it = 0; it < A_IT; it++) {
            int idx = it * 256 + tid;
            int row = idx >> 2, c4 = (idx & 3) * 4;
            float v[4] = {areg[it].x, areg[it].y, areg[it].z, areg[it].w};
#pragma unroll
            for (int u = 0; u < 4; u++) {
                uint32_t hi, lo;
                split_tf32(v[u], hi, lo);
                As_hi[row][c4 + u] = hi;
                As_lo[row][c4 + u] = lo;
            }
        }
#pragma unroll
        for (int it = 0; it < B_IT; it++) {
            int idx = it * 256 + tid;
            int row = idx >> 2, c4 = (idx & 3) * 4;
            float v[4] = {breg[it].x, breg[it].y, breg[it].z, breg[it].w};
#pragma unroll
            for (int u = 0; u < 4; u++) {
                uint32_t hi, lo;
                split_tf32(v[u], hi, lo);
                Bs_hi[row][c4 + u] = hi;
                Bs_lo[row][c4 + u] = lo;
            }
        }
        __syncthreads();

        // prefetch next tile into regs
        if (k0 + BK < K) {
            int kn = k0 + BK;
#pragma unroll
            for (int it = 0; it < A_IT; it++) {
                int idx = it * 256 + tid;
                int row = idx >> 2, c4 = (idx & 3) * 4;
                areg[it] = *reinterpret_cast<const float4*>(
                    &A[(size_t)(m0 + row) * K + kn + c4]);
            }
#pragma unroll
            for (int it = 0; it < B_IT; it++) {
                int idx = it * 256 + tid;
                int row = idx >> 2, c4 = (idx & 3) * 4;
                breg[it] = *reinterpret_cast<const float4*>(
                    &Bm[(size_t)(n0 + row) * K + kn + c4]);
            }
        }

        // compute: two k=8 slices
#pragma unroll
        for (int ks = 0; ks < BK; ks += 8) {
            uint32_t ah[4][4], al[4][4];
#pragma unroll
            for (int i = 0; i < 4; i++) {
                int r = wm0 + i * 16;
                ah[i][0] = As_hi[r + g][ks + q];
                ah[i][1] = As_hi[r + g + 8][ks + q];
                ah[i][2] = As_hi[r + g][ks + q + 4];
                ah[i][3] = As_hi[r + g + 8][ks + q + 4];
                al[i][0] = As_lo[r + g][ks + q];
                al[i][1] = As_lo[r + g + 8][ks + q];
                al[i][2] = As_lo[r + g][ks + q + 4];
                al[i][3] = As_lo[r + g + 8][ks + q + 4];
            }
            uint32_t bh[NT][2], bl[NT][2];
#pragma unroll
            for (int j = 0; j < NT; j++) {
                int r = wn0 + j * 8 + g;
                bh[j][0] = Bs_hi[r][ks + q];
                bh[j][1] = Bs_hi[r][ks + q + 4];
                bl[j][0] = Bs_lo[r][ks + q];
                bl[j][1] = Bs_lo[r][ks + q + 4];
            }
#pragma unroll
            for (int i = 0; i < 4; i++)
#pragma unroll
                for (int j = 0; j < NT; j++) {
                    mma_tf32(acc[i][j], ah[i], bh[j]);
                    mma_tf32(acc[i][j], ah[i], bl[j]);
                    mma_tf32(acc[i][j], al[i], bh[j]);
                }
        }
        __syncthreads();
    }

    // epilogue: bias + float2 stores
#pragma unroll
    for (int j = 0; j < NT; j++) {
        int col = n0 + wn0 + j * 8 + q * 2;
        float2 bb = *reinterpret_cast<const float2*>(&bias[col]);
#pragma unroll
        for (int i = 0; i < 4; i++) {
            int row = m0 + wm0 + i * 16 + g;
            float2 o0 = {acc[i][j][0] + bb.x, acc[i][j][1] + bb.y};
            float2 o1 = {acc[i][j][2] + bb.x, acc[i][j][3] + bb.y};
            *reinterpret_cast<float2*>(&C[(size_t)row * N + col]) = o0;
            *reinterpret_cast<float2*>(&C[(size_t)(row + 8) * N + col]) = o1;
        }
    }
}

// =========================================================================
// K2: per-chunk state sums. grid = NBH*NCH (256) blocks, 256 threads.
// =========================================================================
__global__ __launch_bounds__(256) void chunk_sums_kernel()
{
    const int blk = blockIdx.x;
    const int bh = blk / NCH, c = blk % NCH;
    const int b = bh / Hn, h = bh % Hn;

    __shared__ float kc[Dn], ks[Dn], vv[Dn];

    const int tid = threadIdx.x;
    const int d4 = (tid >> 4) * 4;
    const int e4 = (tid & 15) * 4;

    float Sc[4][4], Ss[4][4];
#pragma unroll
    for (int i = 0; i < 4; i++)
#pragma unroll
        for (int j = 0; j < 4; j++) { Sc[i][j] = 0.f; Ss[i][j] = 0.f; }
    float zc = 0.f, zs = 0.f;

    for (int s = 0; s < TC; s++) {
        const int tg = c * TC + s;
        const size_t row = (size_t)(b * Tn + tg) * (3 * En);
        if (tid < Dn) {
            float kraw = g_qkv[row + En + h * Dn + tid];
            float kp = fmaxf(kraw, 0.f);
            float ang = PI_2f * (float)tg / (float)Tn;
            float si, co;
            sincosf(ang, &si, &co);
            kc[tid] = kp * co;
            ks[tid] = kp * si;
        } else if (tid < 2 * Dn) {
            vv[tid - Dn] = g_qkv[row + 2 * En + h * Dn + (tid - Dn)];
        }
        __syncthreads();

        float4 v4  = *reinterpret_cast<const float4*>(&vv[e4]);
        float4 kc4 = *reinterpret_cast<const float4*>(&kc[d4]);
        float4 ks4 = *reinterpret_cast<const float4*>(&ks[d4]);
        float va[4] = {v4.x, v4.y, v4.z, v4.w};
        float ca[4] = {kc4.x, kc4.y, kc4.z, kc4.w};
        float sa[4] = {ks4.x, ks4.y, ks4.z, ks4.w};
#pragma unroll
        for (int i = 0; i < 4; i++)
#pragma unroll
            for (int j = 0; j < 4; j++) {
                Sc[i][j] = fmaf(ca[i], va[j], Sc[i][j]);
                Ss[i][j] = fmaf(sa[i], va[j], Ss[i][j]);
            }
        if (tid < Dn) { zc += kc[tid]; zs += ks[tid]; }
        __syncthreads();
    }

    float* st = g_state + (size_t)blk * STATE_STRIDE;
#pragma unroll
    for (int i = 0; i < 4; i++)
#pragma unroll
        for (int j = 0; j < 4; j++) {
            st[(d4 + i) * Dn + e4 + j]        = Sc[i][j];
            st[4096 + (d4 + i) * Dn + e4 + j] = Ss[i][j];
        }
    if (tid < Dn) { st[8192 + tid] = zc; st[8256 + tid] = zs; }
}

// =========================================================================
// K3: exclusive prefix scan over chunks (in place). grid = NBH, 256 threads
// =========================================================================
__global__ __launch_bounds__(256) void scan_states_kernel()
{
    const int bh = blockIdx.x;
    const int tid = threadIdx.x;
    float acc[33];
#pragma unroll
    for (int j = 0; j < 33; j++) acc[j] = 0.f;

    float* base = g_state + (size_t)bh * NCH * STATE_STRIDE;
    for (int c = 0; c < NCH; c++) {
        float* st = base + (size_t)c * STATE_STRIDE;
#pragma unroll
        for (int j = 0; j < 33; j++) {
            int idx = tid + j * 256;
            if (idx < STATE_STRIDE) {
                float t = st[idx];
                st[idx] = acc[j];
                acc[j] += t;
            }
        }
    }
}

// =========================================================================
// K4: per-chunk attention output. grid = NBH*NCH (256), 256 threads.
// =========================================================================
extern __shared__ float k4_smem[];
__global__ __launch_bounds__(256) void attn_chunk_kernel()
{
    const int blk = blockIdx.x;
    const int bh = blk / NCH, c = blk % NCH;
    const int b = bh / Hn, h = bh % Hn;

    float* Qt   = k4_smem;            // [64][68]  Qt[d][t] = relu(q)
    float* Kt   = Qt + 64 * 68;       // [64][68]  Kt[d][s] = relu(k)
    float* Vs   = Kt + 64 * 68;       // [64][64]  Vs[s][e]
    float* Ws   = Vs + 64 * 64;       // [64][64]  W[t][s] (masked)
    float* cosv = Ws + 64 * 64;       // [64]
    float* sinv = cosv + 64;          // [64]
    float* normv = sinv + 64;         // [64]

    const int tid = threadIdx.x;
    const int t4 = (tid >> 4) * 4;
    const int e4 = (tid & 15) * 4;

    // ---- load Q', K', V ----
#pragma unroll
    for (int r = 0; r < 16; r++) {
        int idx = r * 256 + tid;
        int t = idx >> 6, d = idx & 63;
        size_t row = (size_t)(b * Tn + c * TC + t) * (3 * En);
        float qv = fmaxf(g_qkv[row + h * Dn + d], 0.f);
        float kv = fmaxf(g_qkv[row + En + h * Dn + d], 0.f);
        float vv = g_qkv[row + 2 * En + h * Dn + d];
        Qt[d * 68 + t] = qv;
        Kt[d * 68 + t] = kv;
        Vs[t * 64 + d] = vv;
    }
    if (tid < 64) {
        float ang = PI_2f * (float)(c * TC + tid) / (float)Tn;
        float si, co;
        sincosf(ang, &si, &co);
        cosv[tid] = co;
        sinv[tid] = si;
    }
    __syncthreads();

    float ct[4], st4[4], cs[4], ss[4];
#pragma unroll
    for (int i = 0; i < 4; i++) { ct[i] = cosv[t4 + i]; st4[i] = sinv[t4 + i]; }
#pragma unroll
    for (int j = 0; j < 4; j++) { cs[j] = cosv[e4 + j]; ss[j] = sinv[e4 + j]; }

    const float* Pc = g_state + (size_t)blk * STATE_STRIDE;  // exclusive prefix
    const float* Ps = Pc + 4096;

    float ctx[4][4], wacc[4][4];
#pragma unroll
    for (int i = 0; i < 4; i++)
#pragma unroll
        for (int j = 0; j < 4; j++) { ctx[i][j] = 0.f; wacc[i][j] = 0.f; }

    // ---- fused: inter-chunk ctx (q @ P) and raw scores (q @ k^T) ----
#pragma unroll 4
    for (int d = 0; d < 64; d++) {
        float4 q4  = *reinterpret_cast<const float4*>(&Qt[d * 68 + t4]);
        float4 k4  = *reinterpret_cast<const float4*>(&Kt[d * 68 + e4]);
        float4 pc4 = *reinterpret_cast<const float4*>(&Pc[d * 64 + e4]);
        float4 ps4 = *reinterpret_cast<const float4*>(&Ps[d * 64 + e4]);
        float qa[4] = {q4.x, q4.y, q4.z, q4.w};
        float ka[4] = {k4.x, k4.y, k4.z, k4.w};
        float pa[4] = {pc4.x, pc4.y, pc4.z, pc4.w};
        float sa[4] = {ps4.x, ps4.y, ps4.z, ps4.w};
#pragma unroll
        for (int i = 0; i < 4; i++) {
            float qc = qa[i] * ct[i];
            float qs = qa[i] * st4[i];
#pragma unroll
            for (int j = 0; j < 4; j++) {
                wacc[i][j] = fmaf(qa[i], ka[j], wacc[i][j]);
                ctx[i][j]  = fmaf(qc, pa[j], ctx[i][j]);
                ctx[i][j]  = fmaf(qs, sa[j], ctx[i][j]);
            }
        }
    }

    // ---- apply cos(delta) weight + causal mask, write W ----
#pragma unroll
    for (int i = 0; i < 4; i++) {
        int tl = t4 + i;
        float wv[4];
#pragma unroll
        for (int j = 0; j < 4; j++) {
            int sl = e4 + j;
            float f = ct[i] * cs[j] + st4[i] * ss[j];   // cos(ang_t - ang_s)
            wv[j] = (sl <= tl) ? wacc[i][j] * f : 0.f;
        }
        float4 o = {wv[0], wv[1], wv[2], wv[3]};
        *reinterpret_cast<float4*>(&Ws[tl * 64 + e4]) = o;
    }

    // ---- norm, inter-chunk part ----
    if (tid < 64) {
        const float* zc = Pc + 8192;
        const float* zs = Pc + 8256;
        float nc = 0.f, ns = 0.f;
#pragma unroll 8
        for (int d = 0; d < 64; d++) {
            float qv = Qt[d * 68 + tid];
            nc = fmaf(qv, zc[d], nc);
            ns = fmaf(qv, zs[d], ns);
        }
        normv[tid] = cosv[tid] * nc + sinv[tid] * ns;
    }
    __syncthreads();

    // ---- norm, intra part (masked entries are zero so sum whole row) ----
    if (tid < 64) {
        float acc = normv[tid];
        const float* wr = &Ws[tid * 64];
#pragma unroll
        for (int s = 0; s < 64; s += 4) {
            float4 w = *reinterpret_cast<const float4*>(&wr[s]);
            acc += w.x + w.y + w.z + w.w;
        }
        normv[tid] = 1.f / (acc + EPSf);
    }

    // ---- intra-chunk ctx += W @ V ----
#pragma unroll 4
    for (int s = 0; s < 64; s++) {
        float4 v4 = *reinterpret_cast<const float4*>(&Vs[s * 64 + e4]);
        float va[4] = {v4.x, v4.y, v4.z, v4.w};
        float wv[4];
#pragma unroll
        for (int i = 0; i < 4; i++) wv[i] = Ws[(t4 + i) * 64 + s];
#pragma unroll
        for (int i = 0; i < 4; i++)
#pragma unroll
            for (int j = 0; j < 4; j++)
                ctx[i][j] = fmaf(wv[i], va[j], ctx[i][j]);
    }
    __syncthreads();

    // ---- normalize and write ----
#pragma unroll
    for (int i = 0; i < 4; i++) {
        float rn = normv[t4 + i];
        float4 o;
        o.x = ctx[i][0] * rn;
        o.y = ctx[i][1] * rn;
        o.z = ctx[i][2] * rn;
        o.w = ctx[i][3] * rn;
        *reinterpret_cast<float4*>(
            &g_attn[(size_t)(b * Tn + c * TC + t4 + i) * En + h * Dn + e4]) = o;
    }
}

// =========================================================================
// launch
// =========================================================================
extern "C" void kernel_launch(void* const* d_in, const int* in_sizes, int n_in,
                              void* d_out, int out_size)
{
    const float* x      = (const float*)d_in[0];
    const float* w_qkv  = (const float*)d_in[1];
    const float* b_qkv  = (const float*)d_in[2];
    const float* w_out  = (const float*)d_in[3];
    const float* b_out  = (const float*)d_in[4];
    float* out = (float*)d_out;

    float *p_qkv = nullptr, *p_attn = nullptr;
    cudaGetSymbolAddress((void**)&p_qkv, g_qkv);
    cudaGetSymbolAddress((void**)&p_attn, g_attn);

    const int K4_SMEM = (2 * 64 * 68 + 2 * 64 * 64 + 3 * 64) * (int)sizeof(float); // 68352
    cudaFuncSetAttribute(attn_chunk_kernel,
                         cudaFuncAttributeMaxDynamicSharedMemorySize, K4_SMEM);

    // 1) qkv = x @ w_qkv^T + b_qkv   [2048 x 1536], tf32 TC
    {
        dim3 grid((3 * En) / 128, (Bsz * Tn) / 128);   // (12, 16)
        gemm_tf32_nt_bias<128><<<grid, 256>>>(x, w_qkv, b_qkv, p_qkv,
                                              Bsz * Tn, 3 * En, En);
    }
    // 2) per-chunk state sums
    chunk_sums_kernel<<<NBH * NCH, 256>>>();
    // 3) exclusive scan over chunks
    scan_states_kernel<<<NBH, 256>>>();
    // 4) per-chunk attention
    attn_chunk_kernel<<<NBH * NCH, 256, K4_SMEM>>>();
    // 5) out = attn @ w_out^T + b_out   [2048 x 512], tf32 TC
    {
        dim3 grid(En / 64, (Bsz * Tn) / 128);          // (8, 16)
        gemm_tf32_nt_bias<64><<<grid, 256>>>(p_attn, w_out, b_out, out,
                                             Bsz * Tn, En, En);
    }
}

// round 16
// speedup vs baseline: 1.6411x; 1.6411x over previous
#include <cuda_runtime.h>
#include <cuda_bf16.h>
#include <math.h>
#include <stdint.h>

// Problem constants
#define Bsz 2
#define Tn  1024
#define En  512
#define Hn  8
#define Dn  64
#define TC  64                 // chunk length
#define NCH (Tn / TC)          // 16 chunks
#define NBH (Bsz * Hn)         // 16 (b,h) pairs
#define STATE_STRIDE 8320      // Scos(4096) + Ssin(4096) + zc(64) + zs(64)
#define PI_2f 1.5707963267948966f
#define EPSf  1e-6f
#define GK  512                // inner K of both GEMMs

// ---------------- scratch (no runtime allocation allowed) ----------------
__device__ float g_qkv[Bsz * Tn * 3 * En];                 // [2048][1536]  12MB
__device__ float g_state[NBH * NCH * STATE_STRIDE];        // 8.1MB
__device__ float g_attn[Bsz * Tn * En];                    // [2048][512]   4MB

// =========================================================================
// helpers
// =========================================================================
__device__ __forceinline__ uint32_t smem_u32(const void* p) {
    uint32_t a;
    asm("{ .reg .u64 t; cvta.to.shared.u64 t, %1; cvt.u32.u64 %0, t; }"
        : "=r"(a) : "l"(p));
    return a;
}

__device__ __forceinline__ void ldsm_x4(uint32_t r[4], uint32_t addr) {
    asm volatile("ldmatrix.sync.aligned.m8n8.x4.shared.b16 {%0,%1,%2,%3}, [%4];"
                 : "=r"(r[0]), "=r"(r[1]), "=r"(r[2]), "=r"(r[3]) : "r"(addr));
}

__device__ __forceinline__ void mma_bf16(float c[4], const uint32_t a[4],
                                         const uint32_t b[2]) {
    asm volatile(
        "mma.sync.aligned.m16n8k16.row.col.f32.bf16.bf16.f32 "
        "{%0,%1,%2,%3}, {%4,%5,%6,%7}, {%8,%9}, {%0,%1,%2,%3};\n"
        : "+f"(c[0]), "+f"(c[1]), "+f"(c[2]), "+f"(c[3])
        : "r"(a[0]), "r"(a[1]), "r"(a[2]), "r"(a[3]),
          "r"(b[0]), "r"(b[1]));
}

// split a float pair into packed bf16x2 (hi) and packed bf16x2 (lo residual)
__device__ __forceinline__ void split2(float x, float y,
                                       uint32_t& hp, uint32_t& lp) {
    __nv_bfloat16 hx = __float2bfloat16(x);
    __nv_bfloat16 hy = __float2bfloat16(y);
    __nv_bfloat16 lx = __float2bfloat16(x - __bfloat162float(hx));
    __nv_bfloat16 ly = __float2bfloat16(y - __bfloat162float(hy));
    hp = ((uint32_t)__bfloat16_as_ushort(hy) << 16) | __bfloat16_as_ushort(hx);
    lp = ((uint32_t)__bfloat16_as_ushort(ly) << 16) | __bfloat16_as_ushort(lx);
}

// =========================================================================
// K1/K5: C[M,N] = A[M,GK] @ B[N,GK]^T + bias[N]
// bf16 mma.sync m16n8k16 with 2-term precision split (hh + hl + lh).
// BN=128, BK=16, 256 threads, 8 warps as 2(m) x 4(n), warp tile (BM/2) x 32.
// Fragments via ldmatrix from +8-padded smem (stride 24 bf16 = 48B).
// grid = (N/128, M/BM)
// =========================================================================
template<int BM>
__global__ __launch_bounds__(256) void gemm_bf16_nt_bias(
    const float* __restrict__ A, const float* __restrict__ Bm,
    const float* __restrict__ bias, float* __restrict__ C, int N)
{
    constexpr int BN = 128, BK = 16;
    constexpr int LDSA = BK + 8;                 // 24 bf16 = 48B row stride
    constexpr int MT = BM / 32;                  // m16-tiles per warp
    constexpr int A_F4 = (BM * BK) / (4 * 256);  // float4 loads per thread
    constexpr int B_F4 = (BN * BK) / (4 * 256);  // 2
    constexpr int NKT = GK / BK;                 // 32 k-steps

    __shared__ alignas(16) __nv_bfloat16 sAhi[BM * LDSA];
    __shared__ alignas(16) __nv_bfloat16 sAlo[BM * LDSA];
    __shared__ alignas(16) __nv_bfloat16 sBhi[BN * LDSA];
    __shared__ alignas(16) __nv_bfloat16 sBlo[BN * LDSA];

    const int tid = threadIdx.x;
    const int warp = tid >> 5, lane = tid & 31;
    const int g = lane >> 2, q = lane & 3;
    const int m0 = blockIdx.y * BM;
    const int n0 = blockIdx.x * BN;
    const int wm = (warp >> 2) * (BM / 2);       // warp m-origin in tile
    const int wn = (warp & 3) * 32;              // warp n-origin in tile

    // ---- precompute ldmatrix lane addresses ----
    const int lr = lane & 7;
    uint32_t aHiAd[MT], aLoAd[MT];
    {
        int row = wm + ((lane >> 3) & 1) * 8 + lr;
        int col = ((lane >> 4) & 1) * 8;
        uint32_t off = (uint32_t)(row * LDSA + col) * 2;
#pragma unroll
        for (int i = 0; i < MT; i++) {
            aHiAd[i] = smem_u32(sAhi) + off + (uint32_t)(i * 16 * LDSA) * 2;
            aLoAd[i] = smem_u32(sAlo) + off + (uint32_t)(i * 16 * LDSA) * 2;
        }
    }
    uint32_t bHiAd[2], bLoAd[2];
    {
        int row = wn + ((lane >> 4) & 1) * 8 + lr;
        int col = ((lane >> 3) & 1) * 8;
        uint32_t off = (uint32_t)(row * LDSA + col) * 2;
#pragma unroll
        for (int p = 0; p < 2; p++) {
            bHiAd[p] = smem_u32(sBhi) + off + (uint32_t)(p * 16 * LDSA) * 2;
            bLoAd[p] = smem_u32(sBlo) + off + (uint32_t)(p * 16 * LDSA) * 2;
        }
    }

    float acc[MT][4][4];
#pragma unroll
    for (int i = 0; i < MT; i++)
#pragma unroll
        for (int j = 0; j < 4; j++)
#pragma unroll
            for (int u = 0; u < 4; u++) acc[i][j][u] = 0.f;

    // ---- prime prefetch ----
    float4 apf[A_F4], bpf[B_F4];
#pragma unroll
    for (int it = 0; it < A_F4; it++) {
        int f = it * 256 + tid;
        apf[it] = *reinterpret_cast<const float4*>(
            &A[(size_t)(m0 + (f >> 2)) * GK + (f & 3) * 4]);
    }
#pragma unroll
    for (int it = 0; it < B_F4; it++) {
        int f = it * 256 + tid;
        bpf[it] = *reinterpret_cast<const float4*>(
            &Bm[(size_t)(n0 + (f >> 2)) * GK + (f & 3) * 4]);
    }

    for (int kt = 0; kt < NKT; kt++) {
        // ---- stage prefetched regs -> smem (bf16 split) ----
#pragma unroll
        for (int it = 0; it < A_F4; it++) {
            int f = it * 256 + tid;
            int r = f >> 2, c = (f & 3) * 4;
            uint32_t hp, lp;
            split2(apf[it].x, apf[it].y, hp, lp);
            *reinterpret_cast<uint32_t*>(&sAhi[r * LDSA + c]) = hp;
            *reinterpret_cast<uint32_t*>(&sAlo[r * LDSA + c]) = lp;
            split2(apf[it].z, apf[it].w, hp, lp);
            *reinterpret_cast<uint32_t*>(&sAhi[r * LDSA + c + 2]) = hp;
            *reinterpret_cast<uint32_t*>(&sAlo[r * LDSA + c + 2]) = lp;
        }
#pragma unroll
        for (int it = 0; it < B_F4; it++) {
            int f = it * 256 + tid;
            int r = f >> 2, c = (f & 3) * 4;
            uint32_t hp, lp;
            split2(bpf[it].x, bpf[it].y, hp, lp);
            *reinterpret_cast<uint32_t*>(&sBhi[r * LDSA + c]) = hp;
            *reinterpret_cast<uint32_t*>(&sBlo[r * LDSA + c]) = lp;
            split2(bpf[it].z, bpf[it].w, hp, lp);
            *reinterpret_cast<uint32_t*>(&sBhi[r * LDSA + c + 2]) = hp;
            *reinterpret_cast<uint32_t*>(&sBlo[r * LDSA + c + 2]) = lp;
        }
        __syncthreads();

        // ---- prefetch next k tile ----
        if (kt + 1 < NKT) {
            int kn = (kt + 1) * BK;
#pragma unroll
            for (int it = 0; it < A_F4; it++) {
                int f = it * 256 + tid;
                apf[it] = *reinterpret_cast<const float4*>(
                    &A[(size_t)(m0 + (f >> 2)) * GK + kn + (f & 3) * 4]);
            }
#pragma unroll
            for (int it = 0; it < B_F4; it++) {
                int f = it * 256 + tid;
                bpf[it] = *reinterpret_cast<const float4*>(
                    &Bm[(size_t)(n0 + (f >> 2)) * GK + kn + (f & 3) * 4]);
            }
        }

        // ---- fragments via ldmatrix ----
        uint32_t Ah[MT][4], Al[MT][4];
#pragma unroll
        for (int i = 0; i < MT; i++) {
            ldsm_x4(Ah[i], aHiAd[i]);
            ldsm_x4(Al[i], aLoAd[i]);
        }
        uint32_t Bh[4][2], Bl[4][2];
#pragma unroll
        for (int p = 0; p < 2; p++) {
            uint32_t t[4];
            ldsm_x4(t, bHiAd[p]);
            Bh[2 * p][0] = t[0]; Bh[2 * p][1] = t[1];
            Bh[2 * p + 1][0] = t[2]; Bh[2 * p + 1][1] = t[3];
            ldsm_x4(t, bLoAd[p]);
            Bl[2 * p][0] = t[0]; Bl[2 * p][1] = t[1];
            Bl[2 * p + 1][0] = t[2]; Bl[2 * p + 1][1] = t[3];
        }

        // ---- 3-pass split mma ----
#pragma unroll
        for (int i = 0; i < MT; i++)
#pragma unroll
            for (int j = 0; j < 4; j++) {
                mma_bf16(acc[i][j], Ah[i], Bh[j]);
                mma_bf16(acc[i][j], Ah[i], Bl[j]);
                mma_bf16(acc[i][j], Al[i], Bh[j]);
            }
        __syncthreads();
    }

    // ---- epilogue: bias + float2 stores ----
#pragma unroll
    for (int j = 0; j < 4; j++) {
        int col = n0 + wn + j * 8 + q * 2;
        float2 bb = *reinterpret_cast<const float2*>(&bias[col]);
#pragma unroll
        for (int i = 0; i < MT; i++) {
            int row = m0 + wm + i * 16 + g;
            float2 o0 = {acc[i][j][0] + bb.x, acc[i][j][1] + bb.y};
            float2 o1 = {acc[i][j][2] + bb.x, acc[i][j][3] + bb.y};
            *reinterpret_cast<float2*>(&C[(size_t)row * N + col]) = o0;
            *reinterpret_cast<float2*>(&C[(size_t)(row + 8) * N + col]) = o1;
        }
    }
}

// =========================================================================
// K2: per-chunk state sums, gemm-style (one barrier).
//   Scos[d][e] = sum_s kc[s][d]*v[s][e];  ks derived as kc*tan(ang_s).
// grid = NBH*NCH (256), 256 threads.
// =========================================================================
__global__ __launch_bounds__(256) void chunk_sums_kernel()
{
    __shared__ float kc[64][64];
    __shared__ float vs[64][64];
    __shared__ float tanv[64];

    const int blk = blockIdx.x;
    const int bh = blk / NCH, c = blk % NCH;
    const int b = bh / Hn, h = bh % Hn;
    const int tid = threadIdx.x;

    if (tid < 64) {
        float ang = PI_2f * (float)(c * TC + tid) / (float)Tn;
        tanv[tid] = tanf(ang);
    }
#pragma unroll
    for (int it = 0; it < 16; it++) {
        int idx = it * 256 + tid;
        int s = idx >> 6, d = idx & 63;
        int tg = c * TC + s;
        size_t row = (size_t)(b * Tn + tg) * (3 * En);
        float kraw = fmaxf(g_qkv[row + En + h * Dn + d], 0.f);
        float ang = PI_2f * (float)tg / (float)Tn;
        kc[s][d] = kraw * cosf(ang);
        vs[s][d] = g_qkv[row + 2 * En + h * Dn + d];
    }
    __syncthreads();

    const int d4 = (tid >> 4) * 4;
    const int e4 = (tid & 15) * 4;
    float Sc[4][4], Ss[4][4];
#pragma unroll
    for (int i = 0; i < 4; i++)
#pragma unroll
        for (int j = 0; j < 4; j++) { Sc[i][j] = 0.f; Ss[i][j] = 0.f; }

#pragma unroll 4
    for (int s = 0; s < 64; s++) {
        float4 k4 = *reinterpret_cast<const float4*>(&kc[s][d4]);
        float4 v4 = *reinterpret_cast<const float4*>(&vs[s][e4]);
        float tn = tanv[s];
        float ca[4] = {k4.x, k4.y, k4.z, k4.w};
        float va[4] = {v4.x, v4.y, v4.z, v4.w};
#pragma unroll
        for (int i = 0; i < 4; i++) {
            float sa = ca[i] * tn;
#pragma unroll
            for (int j = 0; j < 4; j++) {
                Sc[i][j] = fmaf(ca[i], va[j], Sc[i][j]);
                Ss[i][j] = fmaf(sa,    va[j], Ss[i][j]);
            }
        }
    }

    float* st = g_state + (size_t)blk * STATE_STRIDE;
#pragma unroll
    for (int i = 0; i < 4; i++)
#pragma unroll
        for (int j = 0; j < 4; j++) {
            st[(d4 + i) * Dn + e4 + j]        = Sc[i][j];
            st[4096 + (d4 + i) * Dn + e4 + j] = Ss[i][j];
        }
    if (tid < 64) {
        float zc = 0.f, zs = 0.f;
#pragma unroll 8
        for (int s = 0; s < 64; s++) {
            float kv = kc[s][tid];
            zc += kv;
            zs = fmaf(kv, tanv[s], zs);
        }
        st[8192 + tid] = zc;
        st[8256 + tid] = zs;
    }
}

// =========================================================================
// K3: exclusive prefix scan over chunks (in place). grid = NBH, 256 threads
// =========================================================================
__global__ __launch_bounds__(256) void scan_states_kernel()
{
    const int bh = blockIdx.x;
    const int tid = threadIdx.x;
    float acc[33];
#pragma unroll
    for (int j = 0; j < 33; j++) acc[j] = 0.f;

    float* base = g_state + (size_t)bh * NCH * STATE_STRIDE;
    for (int c = 0; c < NCH; c++) {
        float* st = base + (size_t)c * STATE_STRIDE;
#pragma unroll
        for (int j = 0; j < 33; j++) {
            int idx = tid + j * 256;
            if (idx < STATE_STRIDE) {
                float t = st[idx];
                st[idx] = acc[j];
                acc[j] += t;
            }
        }
    }
}

// =========================================================================
// K4: per-chunk attention output. grid = NBH*NCH (256), 256 threads.
// =========================================================================
extern __shared__ float k4_smem[];
__global__ __launch_bounds__(256) void attn_chunk_kernel()
{
    const int blk = blockIdx.x;
    const int bh = blk / NCH, c = blk % NCH;
    const int b = bh / Hn, h = bh % Hn;

    float* Qt   = k4_smem;            // [64][68]  Qt[d][t] = relu(q)
    float* Kt   = Qt + 64 * 68;       // [64][68]  Kt[d][s] = relu(k)
    float* Vs   = Kt + 64 * 68;       // [64][64]  Vs[s][e]
    float* Ws   = Vs + 64 * 64;       // [64][64]  W[t][s] (masked)
    float* cosv = Ws + 64 * 64;       // [64]
    float* sinv = cosv + 64;          // [64]
    float* normv = sinv + 64;         // [64]

    const int tid = threadIdx.x;
    const int t4 = (tid >> 4) * 4;
    const int e4 = (tid & 15) * 4;

    // ---- load Q', K', V ----
#pragma unroll
    for (int r = 0; r < 16; r++) {
        int idx = r * 256 + tid;
        int t = idx >> 6, d = idx & 63;
        size_t row = (size_t)(b * Tn + c * TC + t) * (3 * En);
        float qv = fmaxf(g_qkv[row + h * Dn + d], 0.f);
        float kv = fmaxf(g_qkv[row + En + h * Dn + d], 0.f);
        float vv = g_qkv[row + 2 * En + h * Dn + d];
        Qt[d * 68 + t] = qv;
        Kt[d * 68 + t] = kv;
        Vs[t * 64 + d] = vv;
    }
    if (tid < 64) {
        float ang = PI_2f * (float)(c * TC + tid) / (float)Tn;
        float si, co;
        sincosf(ang, &si, &co);
        cosv[tid] = co;
        sinv[tid] = si;
    }
    __syncthreads();

    float ct[4], st4[4], cs[4], ss[4];
#pragma unroll
    for (int i = 0; i < 4; i++) { ct[i] = cosv[t4 + i]; st4[i] = sinv[t4 + i]; }
#pragma unroll
    for (int j = 0; j < 4; j++) { cs[j] = cosv[e4 + j]; ss[j] = sinv[e4 + j]; }

    const float* Pc = g_state + (size_t)blk * STATE_STRIDE;  // exclusive prefix
    const float* Ps = Pc + 4096;

    float ctx[4][4], wacc[4][4];
#pragma unroll
    for (int i = 0; i < 4; i++)
#pragma unroll
        for (int j = 0; j < 4; j++) { ctx[i][j] = 0.f; wacc[i][j] = 0.f; }

    // ---- fused: inter-chunk ctx (q @ P) and raw scores (q @ k^T) ----
#pragma unroll 4
    for (int d = 0; d < 64; d++) {
        float4 q4  = *reinterpret_cast<const float4*>(&Qt[d * 68 + t4]);
        float4 k4  = *reinterpret_cast<const float4*>(&Kt[d * 68 + e4]);
        float4 pc4 = *reinterpret_cast<const float4*>(&Pc[d * 64 + e4]);
        float4 ps4 = *reinterpret_cast<const float4*>(&Ps[d * 64 + e4]);
        float qa[4] = {q4.x, q4.y, q4.z, q4.w};
        float ka[4] = {k4.x, k4.y, k4.z, k4.w};
        float pa[4] = {pc4.x, pc4.y, pc4.z, pc4.w};
        float sa[4] = {ps4.x, ps4.y, ps4.z, ps4.w};
#pragma unroll
        for (int i = 0; i < 4; i++) {
            float qc = qa[i] * ct[i];
            float qs = qa[i] * st4[i];
#pragma unroll
            for (int j = 0; j < 4; j++) {
                wacc[i][j] = fmaf(qa[i], ka[j], wacc[i][j]);
                ctx[i][j]  = fmaf(qc, pa[j], ctx[i][j]);
                ctx[i][j]  = fmaf(qs, sa[j], ctx[i][j]);
            }
        }
    }

    // ---- apply cos(delta) weight + causal mask, write W ----
#pragma unroll
    for (int i = 0; i < 4; i++) {
        int tl = t4 + i;
        float wv[4];
#pragma unroll
        for (int j = 0; j < 4; j++) {
            int sl = e4 + j;
            float f = ct[i] * cs[j] + st4[i] * ss[j];   // cos(ang_t - ang_s)
            wv[j] = (sl <= tl) ? wacc[i][j] * f : 0.f;
        }
        float4 o = {wv[0], wv[1], wv[2], wv[3]};
        *reinterpret_cast<float4*>(&Ws[tl * 64 + e4]) = o;
    }

    // ---- norm, inter-chunk part ----
    if (tid < 64) {
        const float* zc = Pc + 8192;
        const float* zs = Pc + 8256;
        float nc = 0.f, ns = 0.f;
#pragma unroll 8
        for (int d = 0; d < 64; d++) {
            float qv = Qt[d * 68 + tid];
            nc = fmaf(qv, zc[d], nc);
            ns = fmaf(qv, zs[d], ns);
        }
        normv[tid] = cosv[tid] * nc + sinv[tid] * ns;
    }
    __syncthreads();

    // ---- norm, intra part (masked entries are zero so sum whole row) ----
    if (tid < 64) {
        float acc = normv[tid];
        const float* wr = &Ws[tid * 64];
#pragma unroll
        for (int s = 0; s < 64; s += 4) {
            float4 w = *reinterpret_cast<const float4*>(&wr[s]);
            acc += w.x + w.y + w.z + w.w;
        }
        normv[tid] = 1.f / (acc + EPSf);
    }

    // ---- intra-chunk ctx += W @ V ----
#pragma unroll 4
    for (int s = 0; s < 64; s++) {
        float4 v4 = *reinterpret_cast<const float4*>(&Vs[s * 64 + e4]);
        float va[4] = {v4.x, v4.y, v4.z, v4.w};
        float wv[4];
#pragma unroll
        for (int i = 0; i < 4; i++) wv[i] = Ws[(t4 + i) * 64 + s];
#pragma unroll
        for (int i = 0; i < 4; i++)
#pragma unroll
            for (int j = 0; j < 4; j++)
                ctx[i][j] = fmaf(wv[i], va[j], ctx[i][j]);
    }
    __syncthreads();

    // ---- normalize and write ----
#pragma unroll
    for (int i = 0; i < 4; i++) {
        float rn = normv[t4 + i];
        float4 o;
        o.x = ctx[i][0] * rn;
        o.y = ctx[i][1] * rn;
        o.z = ctx[i][2] * rn;
        o.w = ctx[i][3] * rn;
        *reinterpret_cast<float4*>(
            &g_attn[(size_t)(b * Tn + c * TC + t4 + i) * En + h * Dn + e4]) = o;
    }
}

// =========================================================================
// launch
// =========================================================================
extern "C" void kernel_launch(void* const* d_in, const int* in_sizes, int n_in,
                              void* d_out, int out_size)
{
    const float* x      = (const float*)d_in[0];
    const float* w_qkv  = (const float*)d_in[1];
    const float* b_qkv  = (const float*)d_in[2];
    const float* w_out  = (const float*)d_in[3];
    const float* b_out  = (const float*)d_in[4];
    float* out = (float*)d_out;

    float *p_qkv = nullptr, *p_attn = nullptr;
    cudaGetSymbolAddress((void**)&p_qkv, g_qkv);
    cudaGetSymbolAddress((void**)&p_attn, g_attn);

    const int K4_SMEM = (2 * 64 * 68 + 2 * 64 * 64 + 3 * 64) * (int)sizeof(float); // 68352
    cudaFuncSetAttribute(attn_chunk_kernel,
                         cudaFuncAttributeMaxDynamicSharedMemorySize, K4_SMEM);

    // 1) qkv = x @ w_qkv^T + b_qkv   [2048 x 1536], bf16-split mma
    {
        dim3 grid((3 * En) / 128, (Bsz * Tn) / 128);   // (12, 16)
        gemm_bf16_nt_bias<128><<<grid, 256>>>(x, w_qkv, b_qkv, p_qkv, 3 * En);
    }
    // 2) per-chunk state sums
    chunk_sums_kernel<<<NBH * NCH, 256>>>();
    // 3) exclusive scan over chunks
    scan_states_kernel<<<NBH, 256>>>();
    // 4) per-chunk attention
    attn_chunk_kernel<<<NBH * NCH, 256, K4_SMEM>>>();
    // 5) out = attn @ w_out^T + b_out   [2048 x 512], bf16-split mma
    {
        dim3 grid(En / 128, (Bsz * Tn) / 64);          // (4, 32)
        gemm_bf16_nt_bias<64><<<grid, 256>>>(p_attn, w_out, b_out, out, En);
    }
}